// round 6
// baseline (speedup 1.0000x reference)
#include <cuda_runtime.h>
#include <math.h>

#define BB 128
#define NN 512
#define HH 128
#define TT 32
#define G4 512
#define SH 46    // weight hh-rows cached in smem (46*4KB = 184KB)

typedef unsigned long long u64;

// ------------------------- device scratch -------------------------
__device__ float  g_te[(size_t)BB * HH * NN];   // tanh(enc_trans): [b][k][n]
__device__ float2 g_Wc[HH * G4];                // [hh][j] = {Wih[j][hh], Whh[j][hh]}
__device__ float  g_W2T[HH * HH];
__device__ float  g_W1T[HH * HH];
__device__ unsigned g_sub[TT * 2];

// ------------------------- f32x2 packed math (sm_100+) -------------------------
__device__ __forceinline__ u64 f2pack(float x, float y) {
    u64 r; asm("mov.b64 %0,{%1,%2};" : "=l"(r) : "f"(x), "f"(y)); return r;
}
__device__ __forceinline__ void f2unpack(u64 p, float& x, float& y) {
    asm("mov.b64 {%0,%1},%2;" : "=f"(x), "=f"(y) : "l"(p));
}
__device__ __forceinline__ u64 f2fma(u64 a, u64 b, u64 c) {
    u64 d; asm("fma.rn.f32x2 %0,%1,%2,%3;" : "=l"(d) : "l"(a), "l"(b), "l"(c)); return d;
}
__device__ __forceinline__ u64 f2mul(u64 a, u64 b) {
    u64 d; asm("mul.rn.f32x2 %0,%1,%2;" : "=l"(d) : "l"(a), "l"(b)); return d;
}

// ------------------------- Threefry-2x32 (JAX partitionable) -------------------------
__device__ __forceinline__ unsigned rotl32(unsigned x, int r) {
    return (x << r) | (x >> (32 - r));
}
__device__ __forceinline__ void tf2x32(unsigned k0, unsigned k1,
                                       unsigned x0, unsigned x1,
                                       unsigned& o0, unsigned& o1) {
    unsigned ks2 = k0 ^ k1 ^ 0x1BD11BDAu;
    x0 += k0; x1 += k1;
#define TF_RND(r) { x0 += x1; x1 = rotl32(x1, r); x1 ^= x0; }
    TF_RND(13) TF_RND(15) TF_RND(26) TF_RND(6)
    x0 += k1; x1 += ks2 + 1u;
    TF_RND(17) TF_RND(29) TF_RND(16) TF_RND(24)
    x0 += ks2; x1 += k0 + 2u;
    TF_RND(13) TF_RND(15) TF_RND(26) TF_RND(6)
    x0 += k0; x1 += k1 + 3u;
    TF_RND(17) TF_RND(29) TF_RND(16) TF_RND(24)
    x0 += k1; x1 += ks2 + 4u;
    TF_RND(13) TF_RND(15) TF_RND(26) TF_RND(6)
    x0 += ks2; x1 += k0 + 5u;
#undef TF_RND
    o0 = x0; o1 = x1;
}

// ------------------------- prep -------------------------
__global__ void k_prep(const float* __restrict__ W_ih, const float* __restrict__ W_hh,
                       const float* __restrict__ W1,   const float* __restrict__ W2) {
    int tid = blockIdx.x * blockDim.x + threadIdx.x;
    const int NT = 64 * 256;
    for (int i = tid; i < G4 * HH; i += NT) {
        int j = i / HH, hh = i % HH;
        g_Wc[hh * G4 + j] = make_float2(W_ih[i], W_hh[i]);
    }
    for (int i = tid; i < HH * HH; i += NT) {
        int k = i / HH, hh = i % HH;
        g_W2T[hh * HH + k] = W2[i];
        g_W1T[hh * HH + k] = W1[i];
    }
    if (tid == 0) {
        unsigned k0 = 0u, k1 = 42u;   // jax.random.key(42)
        for (int t = 0; t < TT; t++) {
            unsigned a0, a1, b0, b1;
            tf2x32(k0, k1, 0u, 0u, a0, a1);
            tf2x32(k0, k1, 0u, 1u, b0, b1);
            g_sub[2 * t] = b0; g_sub[2 * t + 1] = b1;
            k0 = a0; k1 = a1;
        }
    }
}

// ------------------------- enc_trans (unchanged, proven) -------------------------
__global__ __launch_bounds__(128) void k_enc(const float* __restrict__ enc) {
    __shared__ float sA[32 * HH];
    int b = blockIdx.y;
    int n0 = blockIdx.x * 32;
    {
        const float4* src = (const float4*)(enc + ((size_t)b * NN + n0) * HH);
        float4* dst = (float4*)sA;
        for (int i = threadIdx.x; i < 32 * HH / 4; i += 128) dst[i] = src[i];
    }
    __syncthreads();
    int k = threadIdx.x;
    float acc[32];
#pragma unroll
    for (int n = 0; n < 32; n++) acc[n] = 0.f;
#pragma unroll 4
    for (int h = 0; h < HH; h++) {
        float w = g_W1T[h * HH + k];
#pragma unroll
        for (int n = 0; n < 32; n++)
            acc[n] = fmaf(sA[n * HH + h], w, acc[n]);
    }
    float* dst = g_te + ((size_t)b * HH + k) * NN + n0;
#pragma unroll
    for (int n = 0; n < 32; n++) dst[n] = tanhf(acc[n]);
}

// ------------------------- decode: 2 batch rows per block, 1024 threads -------------------------
__global__ __launch_bounds__(1024, 1) void k_decode(const float* __restrict__ enc,
                                                    const float* __restrict__ b_ih,
                                                    const float* __restrict__ b_hh,
                                                    const float* __restrict__ v,
                                                    float* __restrict__ out) {
    extern __shared__ float2 s_wc[];            // [SH*G4] shared weight cache (184 KB)
    __shared__ float2 s_dx2[HH];                // {dec_b0, dec_b1}
    __shared__ float2 s_dy2[HH];                // {hx_b0, hx_b1}
    __shared__ float  s_cx[2][HH];
    __shared__ float2 s_tdd[2][HH];             // {td, td}
    __shared__ float2 s_vtdd[2][HH];            // {v*td, v*td}
    __shared__ float2 s_vd[HH];                 // {v, v}
    __shared__ float  s_gates[2][G4];
    __shared__ float  s_part[8 * NN];           // 16 KB scratch
    __shared__ float  s_score[2][NN];
    __shared__ unsigned char s_mask[2][NN];
    __shared__ float  s_rw[32];
    __shared__ int    s_ri[32];
    __shared__ float  s_rm[32];
    __shared__ int    s_sel[2];
    __shared__ float  s_smax[2];

    const int tid = threadIdx.x, lane = tid & 31, wid = tid >> 5;
    const int bg0 = blockIdx.x * 2;
    const float NEG = __int_as_float(0xff800000);

    {   // one-time weight cache fill
        const float4* s = (const float4*)g_Wc;
        float4* d = (float4*)s_wc;
        for (int i = tid; i < SH * G4 / 2; i += 1024) d[i] = s[i];
    }
    if (tid < HH) {
        s_dy2[tid] = make_float2(0.f, 0.f);
        s_cx[0][tid] = 0.f; s_cx[1][tid] = 0.f;
        float vv = v[tid];
        s_vd[tid] = make_float2(vv, vv);
    }
    if (tid < NN) { s_mask[0][tid] = 0; s_mask[1][tid] = 0; }

    // dec0 = mean over n, both batch rows
    {
        int bs = tid >> 9, r = tid & 511, q = r >> 7, h = r & 127;
        const float* p = enc + ((size_t)(bg0 + bs) * NN + (size_t)q * 128) * HH + h;
        float s = 0.f;
#pragma unroll 8
        for (int n = 0; n < 128; n++) s += p[(size_t)n * HH];
        s_part[tid] = s;
    }
    __syncthreads();
    if (tid < 256) {
        int bs = tid >> 7, h = tid & 127, base = bs * 512 + h;
        float m = (s_part[base] + s_part[base + 128] + s_part[base + 256] + s_part[base + 384]) * (1.0f / NN);
        ((float*)&s_dx2[h])[bs] = m;
    }
    __syncthreads();

    float bias = 0.f;
    if (tid < G4) bias = b_ih[tid] + b_hh[tid];
    const u64 ONE2 = f2pack(1.f, 1.f);

    for (int t = 0; t < TT; t++) {
        // --- Phase 1: gates (both b packed in f32x2), 512 workers ---
        if (tid < G4) {
            u64 a0 = f2pack(bias, 0.f) , a1 = f2pack(0.f, bias);
#pragma unroll 8
            for (int hh = 0; hh < SH; hh += 2) {
                float2 w = s_wc[hh * G4 + tid];
                a0 = f2fma(*(const u64*)&s_dx2[hh], f2pack(w.x, w.x), a0);
                a0 = f2fma(*(const u64*)&s_dy2[hh], f2pack(w.y, w.y), a0);
                float2 w2 = s_wc[(hh + 1) * G4 + tid];
                a1 = f2fma(*(const u64*)&s_dx2[hh + 1], f2pack(w2.x, w2.x), a1);
                a1 = f2fma(*(const u64*)&s_dy2[hh + 1], f2pack(w2.y, w2.y), a1);
            }
#pragma unroll 8
            for (int hh = SH; hh < HH; hh += 2) {
                float2 w = g_Wc[hh * G4 + tid];
                a0 = f2fma(*(const u64*)&s_dx2[hh], f2pack(w.x, w.x), a0);
                a0 = f2fma(*(const u64*)&s_dy2[hh], f2pack(w.y, w.y), a0);
                float2 w2 = g_Wc[(hh + 1) * G4 + tid];
                a1 = f2fma(*(const u64*)&s_dx2[hh + 1], f2pack(w2.x, w2.x), a1);
                a1 = f2fma(*(const u64*)&s_dy2[hh + 1], f2pack(w2.y, w2.y), a1);
            }
            float g0, g1, h0, h1;
            f2unpack(a0, g0, g1); f2unpack(a1, h0, h1);
            s_gates[0][tid] = g0 + h0;
            s_gates[1][tid] = g1 + h1;
        }
        __syncthreads();

        // --- Phase 2: LSTM cell (i,f,g,o) ---
        if (tid < 256) {
            int bs = tid >> 7, h = tid & 127;
            const float* g = s_gates[bs];
            float gi = g[h], gf = g[HH + h], gg = g[2 * HH + h], go = g[3 * HH + h];
            float si = fmaf(0.5f, tanhf(0.5f * gi), 0.5f);
            float sf = fmaf(0.5f, tanhf(0.5f * gf), 0.5f);
            float tg = tanhf(gg);
            float so = fmaf(0.5f, tanhf(0.5f * go), 0.5f);
            float c  = fmaf(sf, s_cx[bs][h], si * tg);
            s_cx[bs][h] = c;
            ((float*)&s_dy2[h])[bs] = so * tanhf(c);
        }
        __syncthreads();

        // --- Phase 3: td = tanh(hx @ W2T), both b ---
        {
            int bs = tid >> 9, r = tid & 511, k = r & 127, q = r >> 7;
            float p = 0.f;
#pragma unroll 8
            for (int hh = q * 32; hh < q * 32 + 32; hh++)
                p = fmaf(((const float*)&s_dy2[hh])[bs], g_W2T[hh * HH + k], p);
            s_part[bs * 512 + q * 128 + k] = p;
        }
        __syncthreads();
        if (tid < 256) {
            int bs = tid >> 7, k = tid & 127, base = bs * 512 + k;
            float td = tanhf(s_part[base] + s_part[base + 128] + s_part[base + 256] + s_part[base + 384]);
            s_tdd[bs][k] = make_float2(td, td);
            float vt = s_vd[k].x * td;
            s_vtdd[bs][k] = make_float2(vt, vt);
        }
        __syncthreads();

        // --- Phase 4a: scores via tanh-add identity, groups-of-4 rational accumulation ---
        {
            int bs = tid >> 9, r = tid & 511, n4 = r & 127, q = r >> 7;
            const float4* tp = (const float4*)(g_te + ((size_t)(bg0 + bs) * HH + q * 32) * NN) + n4;
            float4 a = make_float4(0.f, 0.f, 0.f, 0.f);
#pragma unroll
            for (int g = 0; g < 8; g++) {
                u64 numA = 0ull, denA = ONE2, numB = 0ull, denB = ONE2;
#pragma unroll
                for (int kk = 0; kk < 4; kk++) {
                    int k = q * 32 + g * 4 + kk;
                    float4 te = tp[(size_t)(g * 4 + kk) * (NN / 4)];
                    u64 teA = f2pack(te.x, te.y), teB = f2pack(te.z, te.w);
                    u64 td2 = *(const u64*)&s_tdd[bs][k];
                    u64 vt2 = *(const u64*)&s_vtdd[bs][k];
                    u64 vk2 = *(const u64*)&s_vd[k];
                    u64 nkA = f2fma(vk2, teA, vt2);        // v*(te+td)
                    u64 dkA = f2fma(teA, td2, ONE2);       // 1+te*td
                    numA = f2fma(numA, dkA, f2mul(nkA, denA));
                    denA = f2mul(denA, dkA);
                    u64 nkB = f2fma(vk2, teB, vt2);
                    u64 dkB = f2fma(teB, td2, ONE2);
                    numB = f2fma(numB, dkB, f2mul(nkB, denB));
                    denB = f2mul(denB, dkB);
                }
                float nx, ny, dx, dy;
                f2unpack(numA, nx, ny); f2unpack(denA, dx, dy);
                a.x += __fdividef(nx, dx); a.y += __fdividef(ny, dy);
                f2unpack(numB, nx, ny); f2unpack(denB, dx, dy);
                a.z += __fdividef(nx, dx); a.w += __fdividef(ny, dy);
            }
            ((float4*)s_part)[(bs * 4 + q) * (NN / 4) + n4] = a;
        }
        __syncthreads();

        // --- Phase 4b: combine quarters + gumbel + fused argmax/scoremax (512 workers) ---
        if (tid < 512) {
            int bs = tid >> 8, tt = tid & 255, base = bs * 4 * NN;
            int na = tt, nb = tt + 256;
            float sc0 = s_part[base + na] + s_part[base + NN + na] + s_part[base + 2 * NN + na] + s_part[base + 3 * NN + na];
            float sc1 = s_part[base + nb] + s_part[base + NN + nb] + s_part[base + 2 * NN + nb] + s_part[base + 3 * NN + nb];

            unsigned sk0 = g_sub[2 * t], sk1 = g_sub[2 * t + 1];
            unsigned bb = (unsigned)((bg0 + bs) * NN);
            unsigned o0, o1;
            tf2x32(sk0, sk1, 0u, bb + na, o0, o1);
            unsigned bits0 = o0 ^ o1;
            tf2x32(sk0, sk1, 0u, bb + nb, o0, o1);
            unsigned bits1 = o0 ^ o1;
            float u0 = fmaxf(1.17549435e-38f, __uint_as_float((bits0 >> 9) | 0x3f800000u) - 1.0f);
            float u1 = fmaxf(1.17549435e-38f, __uint_as_float((bits1 >> 9) | 0x3f800000u) - 1.0f);
            float gum0 = -logf(-logf(u0));
            float gum1 = -logf(-logf(u1));

            float sm0 = s_mask[bs][na] ? NEG : sc0;
            float sm1 = s_mask[bs][nb] ? NEG : sc1;
            s_score[bs][na] = sm0;
            s_score[bs][nb] = sm1;

            float p0 = sm0 + gum0, p1 = sm1 + gum1;
            float mv; int mi;
            if (p1 > p0) { mv = p1; mi = nb; } else { mv = p0; mi = na; }
            float sx = fmaxf(sm0, sm1);
#pragma unroll
            for (int off = 16; off; off >>= 1) {
                float ov = __shfl_down_sync(0xffffffffu, mv, off);
                int   oi = __shfl_down_sync(0xffffffffu, mi, off);
                float os = __shfl_down_sync(0xffffffffu, sx, off);
                if (ov > mv || (ov == mv && oi < mi)) { mv = ov; mi = oi; }
                sx = fmaxf(sx, os);
            }
            if (lane == 0) { s_rw[wid] = mv; s_ri[wid] = mi; s_rm[wid] = sx; }
        }
        __syncthreads();
        if (wid == 0 || wid == 8) {     // wid 0 reduces b0 (warps 0-7), wid 8 reduces b1 (8-15)
            int bs = wid >> 3;
            float mv = (lane < 8) ? s_rw[bs * 8 + lane] : NEG;
            int   mi = (lane < 8) ? s_ri[bs * 8 + lane] : 0x7fffffff;
            float sx = (lane < 8) ? s_rm[bs * 8 + lane] : NEG;
#pragma unroll
            for (int off = 4; off; off >>= 1) {
                float ov = __shfl_down_sync(0xffffffffu, mv, off);
                int   oi = __shfl_down_sync(0xffffffffu, mi, off);
                float os = __shfl_down_sync(0xffffffffu, sx, off);
                if (ov > mv || (ov == mv && oi < mi)) { mv = ov; mi = oi; }
                sx = fmaxf(sx, os);
            }
            if (lane == 0) { s_sel[bs] = mi; s_smax[bs] = sx; }
        }
        __syncthreads();

        // --- softmax denominator, both b (1024 workers, one n each) ---
        {
            int bs = tid >> 9, n = tid & 511;
            float e = expf(s_score[bs][n] - s_smax[bs]);
#pragma unroll
            for (int off = 16; off; off >>= 1)
                e += __shfl_down_sync(0xffffffffu, e, off);
            if (lane == 0) s_rw[wid] = e;      // warps 0-15: b0, 16-31: b1
        }
        __syncthreads();

        if (tid == 0 || tid == 512) {
            int bs = tid >> 9;
            float tot = 0.f;
#pragma unroll
            for (int i = 0; i < 16; i++) tot += s_rw[bs * 16 + i];
            int sel = s_sel[bs];
            float prob = expf(s_score[bs][sel] - s_smax[bs]) / tot;
            out[(bg0 + bs) * TT + t]           = (float)sel;
            out[BB * TT + (bg0 + bs) * TT + t] = logf(prob + 1e-9f);
            s_mask[bs][sel] = 1;
        }
        __syncthreads();

        if (tid < 256) {
            int bs = tid >> 7, h = tid & 127;
            ((float*)&s_dx2[h])[bs] = enc[((size_t)(bg0 + bs) * NN + s_sel[bs]) * HH + h];
        }
        __syncthreads();
    }
}

// ------------------------- launcher -------------------------
extern "C" void kernel_launch(void* const* d_in, const int* in_sizes, int n_in,
                              void* d_out, int out_size) {
    const float* enc  = (const float*)d_in[0];
    const float* W_ih = (const float*)d_in[1];
    const float* W_hh = (const float*)d_in[2];
    const float* b_ih = (const float*)d_in[3];
    const float* b_hh = (const float*)d_in[4];
    const float* W1   = (const float*)d_in[5];
    const float* W2   = (const float*)d_in[6];
    const float* v    = (const float*)d_in[7];
    (void)in_sizes; (void)n_in; (void)out_size;

    const int smem = SH * G4 * sizeof(float2);   // 188416 bytes
    cudaFuncSetAttribute(k_decode, cudaFuncAttributeMaxDynamicSharedMemorySize, smem);

    k_prep<<<64, 256>>>(W_ih, W_hh, W1, W2);
    k_enc<<<dim3(16, BB), 128>>>(enc);
    k_decode<<<BB / 2, 1024, smem>>>(enc, b_ih, b_hh, v, (float*)d_out);
}

// round 7
// speedup vs baseline: 1.3898x; 1.3898x over previous
#include <cuda_runtime.h>
#include <math.h>

#define BB 128
#define NN 512
#define HH 128
#define TT 32
#define G4 512
#define SH2 48   // cached hh-rows of this block's j-half (48 * 2KB = 96KB)

typedef unsigned long long u64;

// ------------------------- device scratch -------------------------
__device__ float  g_te[(size_t)BB * HH * NN];   // tanh(enc_trans): [b][k][n]
__device__ float2 g_Wc[HH * G4];                // [hh][j] = {Wih[j][hh], Whh[j][hh]}
__device__ float  g_W2T[HH * HH];               // [hh][k]
__device__ float  g_W1T[HH * HH];               // [hh][k]
__device__ unsigned g_sub[TT * 2];

// pairwise mailboxes, fresh slot per (b, t) -> no stale-cache hazards
__device__ float g_mgate[BB * TT * G4];         // 8 MB
__device__ float g_mtd[BB * TT * HH];           // 2 MB
__device__ float g_mstat[BB * TT * 2 * 8];      // 1 MB
__device__ int   g_flag[BB * TT * 6];           // [b][t][phase*2+r], zeroed each launch

// ------------------------- f32x2 packed math -------------------------
__device__ __forceinline__ u64 f2pack(float x, float y) {
    u64 r; asm("mov.b64 %0,{%1,%2};" : "=l"(r) : "f"(x), "f"(y)); return r;
}
__device__ __forceinline__ void f2unpack(u64 p, float& x, float& y) {
    asm("mov.b64 {%0,%1},%2;" : "=f"(x), "=f"(y) : "l"(p));
}
__device__ __forceinline__ u64 f2fma(u64 a, u64 b, u64 c) {
    u64 d; asm("fma.rn.f32x2 %0,%1,%2,%3;" : "=l"(d) : "l"(a), "l"(b), "l"(c)); return d;
}

// ------------------------- Threefry-2x32 (JAX partitionable) -------------------------
__device__ __forceinline__ unsigned rotl32(unsigned x, int r) {
    return (x << r) | (x >> (32 - r));
}
__device__ __forceinline__ void tf2x32(unsigned k0, unsigned k1,
                                       unsigned x0, unsigned x1,
                                       unsigned& o0, unsigned& o1) {
    unsigned ks2 = k0 ^ k1 ^ 0x1BD11BDAu;
    x0 += k0; x1 += k1;
#define TF_RND(r) { x0 += x1; x1 = rotl32(x1, r); x1 ^= x0; }
    TF_RND(13) TF_RND(15) TF_RND(26) TF_RND(6)
    x0 += k1; x1 += ks2 + 1u;
    TF_RND(17) TF_RND(29) TF_RND(16) TF_RND(24)
    x0 += ks2; x1 += k0 + 2u;
    TF_RND(13) TF_RND(15) TF_RND(26) TF_RND(6)
    x0 += k0; x1 += k1 + 3u;
    TF_RND(17) TF_RND(29) TF_RND(16) TF_RND(24)
    x0 += k1; x1 += ks2 + 4u;
    TF_RND(13) TF_RND(15) TF_RND(26) TF_RND(6)
    x0 += ks2; x1 += k0 + 5u;
#undef TF_RND
    o0 = x0; o1 = x1;
}

// ------------------------- prep: layouts + subkeys + flag reset -------------------------
__global__ void k_prep(const float* __restrict__ W_ih, const float* __restrict__ W_hh,
                       const float* __restrict__ W1,   const float* __restrict__ W2) {
    int tid = blockIdx.x * blockDim.x + threadIdx.x;
    const int NT = 64 * 256;
    for (int i = tid; i < G4 * HH; i += NT) {
        int j = i / HH, hh = i % HH;
        g_Wc[hh * G4 + j] = make_float2(W_ih[i], W_hh[i]);
    }
    for (int i = tid; i < HH * HH; i += NT) {
        int k = i / HH, hh = i % HH;
        g_W2T[hh * HH + k] = W2[i];
        g_W1T[hh * HH + k] = W1[i];
    }
    for (int i = tid; i < BB * TT * 6; i += NT) g_flag[i] = 0;
    if (tid == 0) {
        unsigned k0 = 0u, k1 = 42u;   // jax.random.key(42)
        for (int t = 0; t < TT; t++) {
            unsigned a0, a1, b0, b1;
            tf2x32(k0, k1, 0u, 0u, a0, a1);
            tf2x32(k0, k1, 0u, 1u, b0, b1);
            g_sub[2 * t] = b0; g_sub[2 * t + 1] = b1;
            k0 = a0; k1 = a1;
        }
    }
}

// ------------------------- enc_trans with f32x2 (same h-order => same bits) -------------
__global__ __launch_bounds__(128) void k_enc(const float* __restrict__ enc) {
    __shared__ float sAT[HH][36];   // [h][n], 36-float rows (16B-aligned, 144B)
    const int b  = blockIdx.y;
    const int n0 = blockIdx.x * 32;
    {
        const float4* src = (const float4*)(enc + ((size_t)b * NN + n0) * HH);
        for (int i = threadIdx.x; i < 32 * 32; i += 128) {
            int n = i >> 5, h4 = (i & 31) << 2;
            float4 vv = src[i];
            sAT[h4 + 0][n] = vv.x;
            sAT[h4 + 1][n] = vv.y;
            sAT[h4 + 2][n] = vv.z;
            sAT[h4 + 3][n] = vv.w;
        }
    }
    __syncthreads();

    const int k = threadIdx.x;
    u64 acc[16];
    const u64 Z = f2pack(0.f, 0.f);
#pragma unroll
    for (int i = 0; i < 16; i++) acc[i] = Z;

#pragma unroll 4
    for (int h = 0; h < HH; h++) {
        float w = __ldg(&g_W1T[h * HH + k]);
        u64 wd = f2pack(w, w);
        const ulonglong2* row = (const ulonglong2*)&sAT[h][0];
#pragma unroll
        for (int i = 0; i < 8; i++) {
            ulonglong2 q = row[i];
            acc[2 * i]     = f2fma(q.x, wd, acc[2 * i]);
            acc[2 * i + 1] = f2fma(q.y, wd, acc[2 * i + 1]);
        }
    }
    float2* dst = (float2*)(g_te + ((size_t)b * HH + k) * NN + n0);
#pragma unroll
    for (int i = 0; i < 16; i++) {
        float a, bb;
        f2unpack(acc[i], a, bb);
        dst[i] = make_float2(tanhf(a), tanhf(bb));
    }
}

// ------------------------- decode: 2 cooperating blocks per batch row ---------------------
// block (2b + r): r = j-half (gates), k-half (td), n-half (scores)
__global__ __launch_bounds__(256, 2) void k_decode(const float* __restrict__ enc,
                                                   const float* __restrict__ b_ih,
                                                   const float* __restrict__ b_hh,
                                                   const float* __restrict__ v,
                                                   float* __restrict__ out) {
    extern __shared__ float2 s_wc[];          // [SH2 * 256] this block's j-half rows (96 KB)
    __shared__ float s_gates[G4];
    __shared__ float s_hx[HH], s_cx[HH], s_dec[HH], s_td[HH], s_v[HH];
    __shared__ unsigned char s_mask[NN];
    __shared__ float s_rw[8]; __shared__ int s_ri[8];
    __shared__ float s_rs[8]; __shared__ float s_rm[8]; __shared__ float s_re[8];
    __shared__ int   s_sel;
    __shared__ float s_bc[2];

    const int tid  = threadIdx.x;
    const int lane = tid & 31, wid = tid >> 5;
    const int b = blockIdx.x >> 1, r = blockIdx.x & 1;
    const int j0 = r * 256, k0 = r * 64, n0 = r * 256;
    const float NEG = __int_as_float(0xff800000);

    // one-time weight cache fill (this block's j-half of rows 0..SH2)
    for (int i = tid; i < SH2 * 256; i += 256) {
        int hh = i >> 8, jj = i & 255;
        s_wc[i] = g_Wc[hh * G4 + j0 + jj];
    }
    if (tid < HH) { s_hx[tid] = 0.f; s_cx[tid] = 0.f; s_v[tid] = v[tid]; }
    s_mask[tid] = 0; s_mask[tid + 256] = 0;

    // dec0 = mean over n (duplicated in both blocks; identical arithmetic)
    {
        int half = tid >> 7, h = tid & 127;
        const float* p = enc + ((size_t)b * NN + (size_t)half * 256) * HH + h;
        float sum = 0.f;
#pragma unroll 8
        for (int n = 0; n < 256; n++) sum += p[(size_t)n * HH];
        s_gates[tid] = sum;
        __syncthreads();
        if (tid < HH) s_dec[tid] = (s_gates[tid] + s_gates[tid + 128]) * (1.0f / NN);
    }
    __syncthreads();

    const float bias = __ldg(&b_ih[j0 + tid]) + __ldg(&b_hh[j0 + tid]);

    for (int t = 0; t < TT; t++) {
        float* mgate = g_mgate + (size_t)(b * TT + t) * G4;
        float* mtd   = g_mtd   + (size_t)(b * TT + t) * HH;
        float* mst   = g_mstat + (size_t)(b * TT + t) * 16;
        int*   flg   = g_flag  + (b * TT + t) * 6;

        // --- Phase 1: gates for this j-half ---
        {
            float acc = bias;
#pragma unroll 8
            for (int hh = 0; hh < SH2; hh++) {
                float2 w = s_wc[hh * 256 + tid];
                acc = fmaf(s_dec[hh], w.x, acc);
                acc = fmaf(s_hx[hh],  w.y, acc);
            }
#pragma unroll 8
            for (int hh = SH2; hh < HH; hh++) {
                float2 w = __ldg(&g_Wc[hh * G4 + j0 + tid]);
                acc = fmaf(s_dec[hh], w.x, acc);
                acc = fmaf(s_hx[hh],  w.y, acc);
            }
            s_gates[j0 + tid] = acc;
            __stcg(&mgate[j0 + tid], acc);
        }
        __syncthreads();
        if (tid == 0) {
            __threadfence();
            atomicExch(&flg[0 * 2 + r], 1);
            while (atomicAdd(&flg[0 * 2 + (r ^ 1)], 0) == 0) { }
            __threadfence();
        }
        __syncthreads();
        {
            int pj = (r ^ 1) * 256 + tid;
            s_gates[pj] = __ldcg(&mgate[pj]);
        }
        __syncthreads();

        // --- Phase 2: LSTM cell (duplicated; identical bits in both blocks) ---
        if (tid < HH) {
            float gi = s_gates[tid], gf = s_gates[HH + tid];
            float gg = s_gates[2 * HH + tid], go = s_gates[3 * HH + tid];
            float si = fmaf(0.5f, tanhf(0.5f * gi), 0.5f);
            float sf = fmaf(0.5f, tanhf(0.5f * gf), 0.5f);
            float tg = tanhf(gg);
            float so = fmaf(0.5f, tanhf(0.5f * go), 0.5f);
            float c  = fmaf(sf, s_cx[tid], si * tg);
            s_cx[tid] = c;
            s_hx[tid] = so * tanhf(c);
        }
        __syncthreads();

        // --- Phase 3: td for this k-half (4 threads per k) ---
        {
            int kq = tid >> 2, part = tid & 3;
            int k = k0 + kq;
            float p = 0.f;
            const float* wp = g_W2T + (part * 32) * HH + k;
#pragma unroll
            for (int i = 0; i < 32; i++)
                p = fmaf(s_hx[part * 32 + i], wp[i * HH], p);
            p += __shfl_down_sync(0xffffffffu, p, 2);
            p += __shfl_down_sync(0xffffffffu, p, 1);
            if (part == 0) {
                float td = tanhf(p);
                s_td[k] = td;
                __stcg(&mtd[k], td);
            }
        }
        __syncthreads();
        if (tid == 0) {
            __threadfence();
            atomicExch(&flg[1 * 2 + r], 1);
            while (atomicAdd(&flg[1 * 2 + (r ^ 1)], 0) == 0) { }
            __threadfence();
        }
        __syncthreads();
        if (tid < 64) {
            int pk = (r ^ 1) * 64 + tid;
            s_td[pk] = __ldcg(&mtd[pk]);
        }
        __syncthreads();

        // --- Phase 4: scores for this n-half + gumbel + reductions ---
        float mvL, mscL, sxL; int miL;
        float sm;
        {
            const int n = n0 + tid;
            const float* tp = g_te + (size_t)b * HH * NN + n;
            float s = 0.f;
#pragma unroll 16
            for (int k = 0; k < HH; k++) {
                float te = __ldg(tp + (size_t)k * NN);
                float td = s_td[k];
                s = fmaf(s_v[k], __fdividef(te + td, fmaf(te, td, 1.f)), s);
            }
            unsigned sk0 = g_sub[2 * t], sk1 = g_sub[2 * t + 1];
            unsigned o0, o1;
            tf2x32(sk0, sk1, 0u, (unsigned)(b * NN + n), o0, o1);
            unsigned bits = o0 ^ o1;
            float u = fmaxf(1.17549435e-38f, __uint_as_float((bits >> 9) | 0x3f800000u) - 1.0f);
            float gum = -logf(-logf(u));

            sm = s_mask[n] ? NEG : s;
            float p = sm + gum;
            float mv = p; int mi = n; float msc = sm; float sx = sm;
#pragma unroll
            for (int off = 16; off; off >>= 1) {
                float ov = __shfl_down_sync(0xffffffffu, mv, off);
                int   oi = __shfl_down_sync(0xffffffffu, mi, off);
                float oc = __shfl_down_sync(0xffffffffu, msc, off);
                float os = __shfl_down_sync(0xffffffffu, sx, off);
                if (ov > mv || (ov == mv && oi < mi)) { mv = ov; mi = oi; msc = oc; }
                sx = fmaxf(sx, os);
            }
            if (lane == 0) { s_rw[wid] = mv; s_ri[wid] = mi; s_rs[wid] = msc; s_rm[wid] = sx; }
        }
        __syncthreads();
        if (tid == 0) {
            mvL = s_rw[0]; miL = s_ri[0]; mscL = s_rs[0]; sxL = s_rm[0];
#pragma unroll
            for (int w = 1; w < 8; w++) {
                if (s_rw[w] > mvL || (s_rw[w] == mvL && s_ri[w] < miL)) {
                    mvL = s_rw[w]; miL = s_ri[w]; mscL = s_rs[w];
                }
                sxL = fmaxf(sxL, s_rm[w]);
            }
            s_bc[0] = sxL;
        }
        __syncthreads();
        {
            float e = expf(sm - s_bc[0]);   // exp(-inf)=0 for masked
#pragma unroll
            for (int off = 16; off; off >>= 1)
                e += __shfl_down_sync(0xffffffffu, e, off);
            if (lane == 0) s_re[wid] = e;
        }
        __syncthreads();

        if (tid == 0) {
            float sumL = 0.f;
#pragma unroll
            for (int w = 0; w < 8; w++) sumL += s_re[w];
            __stcg(&mst[r * 8 + 0], mvL);
            __stcg(&mst[r * 8 + 1], __int_as_float(miL));
            __stcg(&mst[r * 8 + 2], mscL);
            __stcg(&mst[r * 8 + 3], sxL);
            __stcg(&mst[r * 8 + 4], sumL);
            __threadfence();
            atomicExch(&flg[2 * 2 + r], 1);
            while (atomicAdd(&flg[2 * 2 + (r ^ 1)], 0) == 0) { }
            __threadfence();
            int pr = r ^ 1;
            float mvP  = __ldcg(&mst[pr * 8 + 0]);
            int   miP  = __float_as_int(__ldcg(&mst[pr * 8 + 1]));
            float mscP = __ldcg(&mst[pr * 8 + 2]);
            float sxP  = __ldcg(&mst[pr * 8 + 3]);
            float sumP = __ldcg(&mst[pr * 8 + 4]);
            // order by rank: A = rank0 (lower n indices), B = rank1
            float mvA, mscA, sxA, sumA, mvB, mscB, sxB, sumB; int miA, miB;
            if (r == 0) {
                mvA = mvL; miA = miL; mscA = mscL; sxA = sxL; sumA = sumL;
                mvB = mvP; miB = miP; mscB = mscP; sxB = sxP; sumB = sumP;
            } else {
                mvA = mvP; miA = miP; mscA = mscP; sxA = sxP; sumA = sumP;
                mvB = mvL; miB = miL; mscB = mscL; sxB = sxL; sumB = sumL;
            }
            int sel; float mscW;
            if (mvB > mvA) { sel = miB; mscW = mscB; }  // tie -> A (lower index)
            else           { sel = miA; mscW = mscA; }
            float smax = fmaxf(sxA, sxB);
            float tot  = sumA * expf(sxA - smax) + sumB * expf(sxB - smax);
            if (r == 0) {
                float prob = expf(mscW - smax) / tot;
                out[b * TT + t]           = (float)sel;
                out[BB * TT + b * TT + t] = logf(prob + 1e-9f);
            }
            s_sel = sel;
            s_mask[sel] = 1;
        }
        __syncthreads();

        if (tid < HH)
            s_dec[tid] = __ldg(enc + ((size_t)b * NN + s_sel) * HH + tid);
        __syncthreads();
    }
}

// ------------------------- launcher -------------------------
extern "C" void kernel_launch(void* const* d_in, const int* in_sizes, int n_in,
                              void* d_out, int out_size) {
    const float* enc  = (const float*)d_in[0];
    const float* W_ih = (const float*)d_in[1];
    const float* W_hh = (const float*)d_in[2];
    const float* b_ih = (const float*)d_in[3];
    const float* b_hh = (const float*)d_in[4];
    const float* W1   = (const float*)d_in[5];
    const float* W2   = (const float*)d_in[6];
    const float* v    = (const float*)d_in[7];
    (void)in_sizes; (void)n_in; (void)out_size;

    const int smem = SH2 * 256 * sizeof(float2);   // 98304 bytes
    cudaFuncSetAttribute(k_decode, cudaFuncAttributeMaxDynamicSharedMemorySize, smem);

    k_prep<<<64, 256>>>(W_ih, W_hh, W1, W2);
    k_enc<<<dim3(16, BB), 128>>>(enc);
    k_decode<<<BB * 2, 256, smem>>>(enc, b_ih, b_hh, v, (float*)d_out);
}

// round 8
// speedup vs baseline: 1.9804x; 1.4250x over previous
#include <cuda_runtime.h>
#include <math.h>

#define BB 128
#define NN 512
#define HH 128
#define TT 32
#define G4 512
#define SH 52      // weight hh-rows cached in smem (52*4KB = 208KB)
#define REGR 76    // weight hh-rows cached in registers (rows SH..127)

typedef unsigned long long u64;

// ------------------------- device scratch -------------------------
__device__ float  g_te[(size_t)BB * HH * NN];   // tanh(enc_trans): [b][k][n]
__device__ float2 g_Wc[HH * G4];                // [hh][j] = {Wih[j][hh], Whh[j][hh]}
__device__ float  g_W2T[HH * HH];               // [hh][k]
__device__ float  g_W1T[HH * HH];               // [hh][k]
__device__ unsigned g_sub[TT * 2];

// ------------------------- f32x2 packed math (sm_100+) -------------------------
__device__ __forceinline__ u64 f2pack(float x, float y) {
    u64 r; asm("mov.b64 %0,{%1,%2};" : "=l"(r) : "f"(x), "f"(y)); return r;
}
__device__ __forceinline__ void f2unpack(u64 p, float& x, float& y) {
    asm("mov.b64 {%0,%1},%2;" : "=f"(x), "=f"(y) : "l"(p));
}
__device__ __forceinline__ u64 f2fma(u64 a, u64 b, u64 c) {
    u64 d; asm("fma.rn.f32x2 %0,%1,%2,%3;" : "=l"(d) : "l"(a), "l"(b), "l"(c)); return d;
}

// ------------------------- Threefry-2x32 (JAX partitionable) -------------------------
__device__ __forceinline__ unsigned rotl32(unsigned x, int r) {
    return (x << r) | (x >> (32 - r));
}
__device__ __forceinline__ void tf2x32(unsigned k0, unsigned k1,
                                       unsigned x0, unsigned x1,
                                       unsigned& o0, unsigned& o1) {
    unsigned ks2 = k0 ^ k1 ^ 0x1BD11BDAu;
    x0 += k0; x1 += k1;
#define TF_RND(r) { x0 += x1; x1 = rotl32(x1, r); x1 ^= x0; }
    TF_RND(13) TF_RND(15) TF_RND(26) TF_RND(6)
    x0 += k1; x1 += ks2 + 1u;
    TF_RND(17) TF_RND(29) TF_RND(16) TF_RND(24)
    x0 += ks2; x1 += k0 + 2u;
    TF_RND(13) TF_RND(15) TF_RND(26) TF_RND(6)
    x0 += k0; x1 += k1 + 3u;
    TF_RND(17) TF_RND(29) TF_RND(16) TF_RND(24)
    x0 += k1; x1 += ks2 + 4u;
    TF_RND(13) TF_RND(15) TF_RND(26) TF_RND(6)
    x0 += ks2; x1 += k0 + 5u;
#undef TF_RND
    o0 = x0; o1 = x1;
}

// ------------------------- prep -------------------------
__global__ void k_prep(const float* __restrict__ W_ih, const float* __restrict__ W_hh,
                       const float* __restrict__ W1,   const float* __restrict__ W2) {
    int tid = blockIdx.x * blockDim.x + threadIdx.x;
    const int NT = 64 * 256;
    for (int i = tid; i < G4 * HH; i += NT) {
        int j = i / HH, hh = i % HH;
        g_Wc[hh * G4 + j] = make_float2(W_ih[i], W_hh[i]);
    }
    for (int i = tid; i < HH * HH; i += NT) {
        int k = i / HH, hh = i % HH;
        g_W2T[hh * HH + k] = W2[i];
        g_W1T[hh * HH + k] = W1[i];
    }
    if (tid == 0) {
        unsigned k0 = 0u, k1 = 42u;   // jax.random.key(42)
        for (int t = 0; t < TT; t++) {
            unsigned a0, a1, b0, b1;
            tf2x32(k0, k1, 0u, 0u, a0, a1);
            tf2x32(k0, k1, 0u, 1u, b0, b1);
            g_sub[2 * t] = b0; g_sub[2 * t + 1] = b1;
            k0 = a0; k1 = a1;
        }
    }
}

// ------------------------- enc_trans with f32x2 (same h-order => same bits) -------------
__global__ __launch_bounds__(128) void k_enc(const float* __restrict__ enc) {
    __shared__ float sAT[HH][36];   // [h][n]
    const int b  = blockIdx.y;
    const int n0 = blockIdx.x * 32;
    {
        const float4* src = (const float4*)(enc + ((size_t)b * NN + n0) * HH);
        for (int i = threadIdx.x; i < 32 * 32; i += 128) {
            int n = i >> 5, h4 = (i & 31) << 2;
            float4 vv = src[i];
            sAT[h4 + 0][n] = vv.x;
            sAT[h4 + 1][n] = vv.y;
            sAT[h4 + 2][n] = vv.z;
            sAT[h4 + 3][n] = vv.w;
        }
    }
    __syncthreads();

    const int k = threadIdx.x;
    u64 acc[16];
    const u64 Z = f2pack(0.f, 0.f);
#pragma unroll
    for (int i = 0; i < 16; i++) acc[i] = Z;

#pragma unroll 4
    for (int h = 0; h < HH; h++) {
        float w = __ldg(&g_W1T[h * HH + k]);
        u64 wd = f2pack(w, w);
        const ulonglong2* row = (const ulonglong2*)&sAT[h][0];
#pragma unroll
        for (int i = 0; i < 8; i++) {
            ulonglong2 q = row[i];
            acc[2 * i]     = f2fma(q.x, wd, acc[2 * i]);
            acc[2 * i + 1] = f2fma(q.y, wd, acc[2 * i + 1]);
        }
    }
    float2* dst = (float2*)(g_te + ((size_t)b * HH + k) * NN + n0);
#pragma unroll
    for (int i = 0; i < 16; i++) {
        float a, bb;
        f2unpack(acc[i], a, bb);
        dst[i] = make_float2(tanhf(a), tanhf(bb));
    }
}

// ------------------------- persistent per-batch decode (register weight cache) -----------
__global__ __launch_bounds__(512, 1) void k_decode(const float* __restrict__ enc,
                                                   const float* __restrict__ b_ih,
                                                   const float* __restrict__ b_hh,
                                                   const float* __restrict__ v,
                                                   float* __restrict__ out) {
    extern __shared__ float2 s_wc[];           // [SH * G4] weight cache (208 KB)
    __shared__ float2 s_dh[HH];                // {dec, hx}
    __shared__ float  s_cx[HH], s_td[HH], s_v[HH];
    __shared__ float  s_score[NN];
    __shared__ float  s_scr[4 * NN];           // scratch (8 KB)
    __shared__ unsigned char s_mask[NN];
    __shared__ float  s_rw[16];
    __shared__ int    s_ri[16];
    __shared__ float  s_rm[16];
    __shared__ int    s_sel;
    __shared__ float  s_smax;

    const int b = blockIdx.x;
    const int tid = threadIdx.x;
    const int lane = tid & 31, wid = tid >> 5;
    const float NEG_INF = __int_as_float(0xff800000);

    // one-time smem weight cache fill (rows 0..SH-1)
    {
        const float4* src = (const float4*)g_Wc;
        float4* dst = (float4*)s_wc;
        for (int i = tid; i < SH * G4 / 2; i += 512) dst[i] = src[i];
    }
    // one-time register weight cache (rows SH..127, this thread's j-column)
    float2 rwc[REGR];
#pragma unroll
    for (int i = 0; i < REGR; i++)
        rwc[i] = __ldg(&g_Wc[(SH + i) * G4 + tid]);

    if (tid < HH) { s_cx[tid] = 0.f; s_dh[tid].y = 0.f; s_v[tid] = v[tid]; }
    s_mask[tid] = 0;

    // dec0 = mean over n of encoder_outputs[b]
    {
        int h = tid & 127, q = tid >> 7;
        const float* p = enc + ((size_t)b * NN + (size_t)q * 128) * HH + h;
        float sum = 0.f;
#pragma unroll 8
        for (int n = 0; n < 128; n++) sum += p[(size_t)n * HH];
        s_scr[tid] = sum;
        __syncthreads();
        if (tid < HH)
            s_dh[tid].x = (s_scr[tid] + s_scr[tid + 128] + s_scr[tid + 256] + s_scr[tid + 384]) * (1.0f / NN);
    }
    __syncthreads();

    const float* teb = g_te + (size_t)b * HH * NN;
    const float bias = b_ih[tid] + b_hh[tid];   // j = tid

    for (int t = 0; t < TT; t++) {
        // --- Phase 1: gates[j] = bias + dec.Wih[:,j] + hx.Whh[:,j] (smem + reg cache) ---
        {
            float acc = bias;
#pragma unroll 4
            for (int hh = 0; hh < SH; hh++) {
                float2 w  = s_wc[hh * G4 + tid];
                float2 dh = s_dh[hh];
                acc = fmaf(dh.x, w.x, acc);
                acc = fmaf(dh.y, w.y, acc);
            }
#pragma unroll
            for (int i = 0; i < REGR; i++) {
                float2 w  = rwc[i];
                float2 dh = s_dh[SH + i];
                acc = fmaf(dh.x, w.x, acc);
                acc = fmaf(dh.y, w.y, acc);
            }
            s_scr[tid] = acc;
        }
        __syncthreads();

        // --- Phase 2: LSTM cell (i,f,g,o) ---
        if (tid < HH) {
            float gi = s_scr[tid];
            float gf = s_scr[HH + tid];
            float gg = s_scr[2 * HH + tid];
            float go = s_scr[3 * HH + tid];
            float si = fmaf(0.5f, tanhf(0.5f * gi), 0.5f);
            float sf = fmaf(0.5f, tanhf(0.5f * gf), 0.5f);
            float tg = tanhf(gg);
            float so = fmaf(0.5f, tanhf(0.5f * go), 0.5f);
            float c  = fmaf(sf, s_cx[tid], si * tg);
            s_cx[tid] = c;
            s_dh[tid].y = so * tanhf(c);
        }
        __syncthreads();

        // --- Phase 3: td[k] = tanh(hx . W2T[:,k]) ---
        {
            int k = tid & 127, q = tid >> 7;
            float p = 0.f;
#pragma unroll
            for (int hh = q * 32; hh < q * 32 + 32; hh++)
                p = fmaf(s_dh[hh].y, g_W2T[hh * HH + k], p);
            s_scr[tid] = p;
        }
        __syncthreads();
        if (tid < HH)
            s_td[tid] = tanhf(s_scr[tid] + s_scr[tid + 128] + s_scr[tid + 256] + s_scr[tid + 384]);
        __syncthreads();

        // --- Phase 4a: partial score over k-quarter, float4 across n ---
        {
            int n4 = tid & 127, q = tid >> 7;
            const float4* tp = reinterpret_cast<const float4*>(teb + (size_t)(q * 32) * NN) + n4;
            float4 a = make_float4(0.f, 0.f, 0.f, 0.f);
#pragma unroll 8
            for (int kk = 0; kk < 32; kk++) {
                float4 te = tp[(size_t)kk * (NN / 4)];
                float td = s_td[q * 32 + kk];
                float vk = s_v[q * 32 + kk];
                a.x = fmaf(vk, __fdividef(te.x + td, fmaf(te.x, td, 1.f)), a.x);
                a.y = fmaf(vk, __fdividef(te.y + td, fmaf(te.y, td, 1.f)), a.y);
                a.z = fmaf(vk, __fdividef(te.z + td, fmaf(te.z, td, 1.f)), a.z);
                a.w = fmaf(vk, __fdividef(te.w + td, fmaf(te.w, td, 1.f)), a.w);
            }
            reinterpret_cast<float4*>(s_scr)[q * 128 + n4] = a;
        }
        __syncthreads();

        // --- Phase 4b: combine partials + gumbel + fused argmax/scoremax reduce ---
        {
            float sc = s_scr[tid] + s_scr[NN + tid] + s_scr[2 * NN + tid] + s_scr[3 * NN + tid];

            unsigned sk0 = g_sub[2 * t], sk1 = g_sub[2 * t + 1];
            unsigned idx = (unsigned)(b * NN + tid);
            unsigned o0, o1;
            tf2x32(sk0, sk1, 0u, idx, o0, o1);
            unsigned bits = o0 ^ o1;
            float f   = __uint_as_float((bits >> 9) | 0x3f800000u) - 1.0f;
            float u   = fmaxf(1.17549435e-38f, f);
            float gum = -logf(-logf(u));

            float sm = s_mask[tid] ? NEG_INF : sc;
            s_score[tid] = sm;
            float mv = sm + gum;
            int   mi = tid;
            float sx = sm;
#pragma unroll
            for (int off = 16; off; off >>= 1) {
                float ov = __shfl_down_sync(0xffffffffu, mv, off);
                int   oi = __shfl_down_sync(0xffffffffu, mi, off);
                float os = __shfl_down_sync(0xffffffffu, sx, off);
                if (ov > mv || (ov == mv && oi < mi)) { mv = ov; mi = oi; }
                sx = fmaxf(sx, os);
            }
            if (lane == 0) { s_rw[wid] = mv; s_ri[wid] = mi; s_rm[wid] = sx; }
        }
        __syncthreads();
        if (wid == 0) {
            float mv = (lane < 16) ? s_rw[lane] : NEG_INF;
            int   mi = (lane < 16) ? s_ri[lane] : 0x7fffffff;
            float sx = (lane < 16) ? s_rm[lane] : NEG_INF;
#pragma unroll
            for (int off = 16; off; off >>= 1) {
                float ov = __shfl_down_sync(0xffffffffu, mv, off);
                int   oi = __shfl_down_sync(0xffffffffu, mi, off);
                float os = __shfl_down_sync(0xffffffffu, sx, off);
                if (ov > mv || (ov == mv && oi < mi)) { mv = ov; mi = oi; }
                sx = fmaxf(sx, os);
            }
            if (lane == 0) { s_sel = mi; s_smax = sx; }
        }
        __syncthreads();

        // --- softmax denominator ---
        {
            float e = expf(s_score[tid] - s_smax);
#pragma unroll
            for (int off = 16; off; off >>= 1)
                e += __shfl_down_sync(0xffffffffu, e, off);
            if (lane == 0) s_rw[wid] = e;
        }
        __syncthreads();

        if (tid == 0) {
            float tot = 0.f;
#pragma unroll
            for (int i = 0; i < 16; i++) tot += s_rw[i];
            int sel = s_sel;
            float prob = expf(s_score[sel] - s_smax) / tot;
            out[b * TT + t]           = (float)sel;
            out[BB * TT + b * TT + t] = logf(prob + 1e-9f);
            s_mask[sel] = 1;
        }
        __syncthreads();

        if (tid < HH)
            s_dh[tid].x = enc[((size_t)b * NN + s_sel) * HH + tid];
        __syncthreads();
    }
}

// ------------------------- launcher -------------------------
extern "C" void kernel_launch(void* const* d_in, const int* in_sizes, int n_in,
                              void* d_out, int out_size) {
    const float* enc  = (const float*)d_in[0];
    const float* W_ih = (const float*)d_in[1];
    const float* W_hh = (const float*)d_in[2];
    const float* b_ih = (const float*)d_in[3];
    const float* b_hh = (const float*)d_in[4];
    const float* W1   = (const float*)d_in[5];
    const float* W2   = (const float*)d_in[6];
    const float* v    = (const float*)d_in[7];
    (void)in_sizes; (void)n_in; (void)out_size;

    const int smem = SH * G4 * sizeof(float2);   // 212992 bytes
    cudaFuncSetAttribute(k_decode, cudaFuncAttributeMaxDynamicSharedMemorySize, smem);

    k_prep<<<64, 256>>>(W_ih, W_hh, W1, W2);
    k_enc<<<dim3(16, BB), 128>>>(enc);
    k_decode<<<BB, 512, smem>>>(enc, b_ih, b_hh, v, (float*)d_out);
}

// round 9
// speedup vs baseline: 2.2071x; 1.1144x over previous
#include <cuda_runtime.h>
#include <math.h>

#define BB 128
#define NN 512
#define HH 128
#define TT 32
#define G4 512
#define SH 52      // weight hh-rows cached in smem (52*4KB = 208KB)
#define REGR 76    // weight hh-rows cached in registers (rows SH..127)

typedef unsigned long long u64;

// ------------------------- device scratch -------------------------
__device__ float  g_te[(size_t)BB * HH * NN];   // tanh(enc_trans): [b][k][n]
__device__ float2 g_Wc[HH * G4];                // [hh][j] = {Wih[j][hh], Whh[j][hh]}
__device__ float  g_W2T[HH * HH];               // [hh][k]
__device__ float  g_W1T[HH * HH];               // [hh][k]
__device__ unsigned g_sub[TT * 2];
__device__ float  g_gum[BB * TT * NN];          // precomputed gumbel noise (8 MB)

// ------------------------- f32x2 packed math (sm_100+) -------------------------
__device__ __forceinline__ u64 f2pack(float x, float y) {
    u64 r; asm("mov.b64 %0,{%1,%2};" : "=l"(r) : "f"(x), "f"(y)); return r;
}
__device__ __forceinline__ void f2unpack(u64 p, float& x, float& y) {
    asm("mov.b64 {%0,%1},%2;" : "=f"(x), "=f"(y) : "l"(p));
}
__device__ __forceinline__ u64 f2fma(u64 a, u64 b, u64 c) {
    u64 d; asm("fma.rn.f32x2 %0,%1,%2,%3;" : "=l"(d) : "l"(a), "l"(b), "l"(c)); return d;
}
__device__ __forceinline__ u64 f2mul(u64 a, u64 b) {
    u64 d; asm("mul.rn.f32x2 %0,%1,%2;" : "=l"(d) : "l"(a), "l"(b)); return d;
}

// ------------------------- Threefry-2x32 (JAX partitionable) -------------------------
__device__ __forceinline__ unsigned rotl32(unsigned x, int r) {
    return (x << r) | (x >> (32 - r));
}
__device__ __forceinline__ void tf2x32(unsigned k0, unsigned k1,
                                       unsigned x0, unsigned x1,
                                       unsigned& o0, unsigned& o1) {
    unsigned ks2 = k0 ^ k1 ^ 0x1BD11BDAu;
    x0 += k0; x1 += k1;
#define TF_RND(r) { x0 += x1; x1 = rotl32(x1, r); x1 ^= x0; }
    TF_RND(13) TF_RND(15) TF_RND(26) TF_RND(6)
    x0 += k1; x1 += ks2 + 1u;
    TF_RND(17) TF_RND(29) TF_RND(16) TF_RND(24)
    x0 += ks2; x1 += k0 + 2u;
    TF_RND(13) TF_RND(15) TF_RND(26) TF_RND(6)
    x0 += k0; x1 += k1 + 3u;
    TF_RND(17) TF_RND(29) TF_RND(16) TF_RND(24)
    x0 += k1; x1 += ks2 + 4u;
    TF_RND(13) TF_RND(15) TF_RND(26) TF_RND(6)
    x0 += ks2; x1 += k0 + 5u;
#undef TF_RND
    o0 = x0; o1 = x1;
}

// ------------------------- prep -------------------------
__global__ void k_prep(const float* __restrict__ W_ih, const float* __restrict__ W_hh,
                       const float* __restrict__ W1,   const float* __restrict__ W2) {
    int tid = blockIdx.x * blockDim.x + threadIdx.x;
    const int NT = 64 * 256;
    for (int i = tid; i < G4 * HH; i += NT) {
        int j = i / HH, hh = i % HH;
        g_Wc[hh * G4 + j] = make_float2(W_ih[i], W_hh[i]);
    }
    for (int i = tid; i < HH * HH; i += NT) {
        int k = i / HH, hh = i % HH;
        g_W2T[hh * HH + k] = W2[i];
        g_W1T[hh * HH + k] = W1[i];
    }
    if (tid == 0) {
        unsigned k0 = 0u, k1 = 42u;   // jax.random.key(42)
        for (int t = 0; t < TT; t++) {
            unsigned a0, a1, b0, b1;
            tf2x32(k0, k1, 0u, 0u, a0, a1);
            tf2x32(k0, k1, 0u, 1u, b0, b1);
            g_sub[2 * t] = b0; g_sub[2 * t + 1] = b1;
            k0 = a0; k1 = a1;
        }
    }
}

// ------------------------- gumbel table: g_gum[(b*TT+t)*NN+n] -------------------------
__global__ __launch_bounds__(512) void k_gum() {
    int idx = blockIdx.x * 512 + threadIdx.x;   // 0 .. BB*TT*NN-1
    int n  = idx & (NN - 1);
    int bt = idx >> 9;
    int t  = bt & (TT - 1);
    int b  = bt >> 5;
    unsigned sk0 = g_sub[2 * t], sk1 = g_sub[2 * t + 1];
    unsigned o0, o1;
    tf2x32(sk0, sk1, 0u, (unsigned)(b * NN + n), o0, o1);
    unsigned bits = o0 ^ o1;
    float u = fmaxf(1.17549435e-38f, __uint_as_float((bits >> 9) | 0x3f800000u) - 1.0f);
    g_gum[idx] = -logf(-logf(u));
}

// ------------------------- enc_trans with f32x2 (same h-order => same bits) -------------
__global__ __launch_bounds__(128) void k_enc(const float* __restrict__ enc) {
    __shared__ float sAT[HH][36];   // [h][n]
    const int b  = blockIdx.y;
    const int n0 = blockIdx.x * 32;
    {
        const float4* src = (const float4*)(enc + ((size_t)b * NN + n0) * HH);
        for (int i = threadIdx.x; i < 32 * 32; i += 128) {
            int n = i >> 5, h4 = (i & 31) << 2;
            float4 vv = src[i];
            sAT[h4 + 0][n] = vv.x;
            sAT[h4 + 1][n] = vv.y;
            sAT[h4 + 2][n] = vv.z;
            sAT[h4 + 3][n] = vv.w;
        }
    }
    __syncthreads();

    const int k = threadIdx.x;
    u64 acc[16];
    const u64 Z = f2pack(0.f, 0.f);
#pragma unroll
    for (int i = 0; i < 16; i++) acc[i] = Z;

#pragma unroll 4
    for (int h = 0; h < HH; h++) {
        float w = __ldg(&g_W1T[h * HH + k]);
        u64 wd = f2pack(w, w);
        const ulonglong2* row = (const ulonglong2*)&sAT[h][0];
#pragma unroll
        for (int i = 0; i < 8; i++) {
            ulonglong2 q = row[i];
            acc[2 * i]     = f2fma(q.x, wd, acc[2 * i]);
            acc[2 * i + 1] = f2fma(q.y, wd, acc[2 * i + 1]);
        }
    }
    float2* dst = (float2*)(g_te + ((size_t)b * HH + k) * NN + n0);
#pragma unroll
    for (int i = 0; i < 16; i++) {
        float a, bb;
        f2unpack(acc[i], a, bb);
        dst[i] = make_float2(tanhf(a), tanhf(bb));
    }
}

// ------------------------- persistent per-batch decode -------------------------
__global__ __launch_bounds__(512, 1) void k_decode(const float* __restrict__ enc,
                                                   const float* __restrict__ b_ih,
                                                   const float* __restrict__ b_hh,
                                                   const float* __restrict__ v,
                                                   float* __restrict__ out) {
    extern __shared__ float2 s_wc[];           // [SH * G4] weight cache (208 KB)
    __shared__ float2 s_dh[HH];                // {dec, hx}
    __shared__ float  s_cx[HH], s_v[HH];
    __shared__ float2 s_td2[HH];               // {td, td}
    __shared__ float2 s_vtd2[HH];              // {v*td, v*td}
    __shared__ float2 s_v2[HH];                // {v, v}
    __shared__ float  s_score[NN];
    __shared__ float  s_scr[4 * NN];           // scratch (8 KB)
    __shared__ unsigned char s_mask[NN];
    __shared__ float  s_rw[16];
    __shared__ int    s_ri[16];
    __shared__ float  s_rm[16];
    __shared__ int    s_sel;
    __shared__ float  s_smax;

    const int b = blockIdx.x;
    const int tid = threadIdx.x;
    const int lane = tid & 31, wid = tid >> 5;
    const float NEG_INF = __int_as_float(0xff800000);

    // one-time smem weight cache fill (rows 0..SH-1)
    {
        const float4* src = (const float4*)g_Wc;
        float4* dst = (float4*)s_wc;
        for (int i = tid; i < SH * G4 / 2; i += 512) dst[i] = src[i];
    }
    // one-time register weight cache (rows SH..127, this thread's j-column), packed u64
    u64 rwc[REGR];
#pragma unroll
    for (int i = 0; i < REGR; i++) {
        float2 w = __ldg(&g_Wc[(SH + i) * G4 + tid]);
        rwc[i] = f2pack(w.x, w.y);
    }

    if (tid < HH) {
        s_cx[tid] = 0.f; s_dh[tid].y = 0.f;
        float vv = v[tid];
        s_v[tid] = vv;
        s_v2[tid] = make_float2(vv, vv);
    }
    s_mask[tid] = 0;

    // dec0 = mean over n of encoder_outputs[b]
    {
        int h = tid & 127, q = tid >> 7;
        const float* p = enc + ((size_t)b * NN + (size_t)q * 128) * HH + h;
        float sum = 0.f;
#pragma unroll 8
        for (int n = 0; n < 128; n++) sum += p[(size_t)n * HH];
        s_scr[tid] = sum;
        __syncthreads();
        if (tid < HH)
            s_dh[tid].x = (s_scr[tid] + s_scr[tid + 128] + s_scr[tid + 256] + s_scr[tid + 384]) * (1.0f / NN);
    }
    __syncthreads();

    const float* teb = g_te + (size_t)b * HH * NN;
    const float bias = b_ih[tid] + b_hh[tid];   // j = tid
    const u64 ONE2 = f2pack(1.f, 1.f);

    for (int t = 0; t < TT; t++) {
        // --- Phase 1: gates[j] via FFMA2: (dec,hx) . (wx,wy), horizontal add at end ---
        {
            u64 acc2 = f2pack(bias, 0.f);
            const u64* dh64 = (const u64*)s_dh;
            const u64* sw64 = (const u64*)s_wc;
#pragma unroll 4
            for (int hh = 0; hh < SH; hh++)
                acc2 = f2fma(dh64[hh], sw64[hh * G4 + tid], acc2);
#pragma unroll
            for (int i = 0; i < REGR; i++)
                acc2 = f2fma(dh64[SH + i], rwc[i], acc2);
            float ax, ay;
            f2unpack(acc2, ax, ay);
            s_scr[tid] = ax + ay;
        }
        __syncthreads();

        // --- Phase 2: LSTM cell (i,f,g,o) ---
        if (tid < HH) {
            float gi = s_scr[tid];
            float gf = s_scr[HH + tid];
            float gg = s_scr[2 * HH + tid];
            float go = s_scr[3 * HH + tid];
            float si = fmaf(0.5f, tanhf(0.5f * gi), 0.5f);
            float sf = fmaf(0.5f, tanhf(0.5f * gf), 0.5f);
            float tg = tanhf(gg);
            float so = fmaf(0.5f, tanhf(0.5f * go), 0.5f);
            float c  = fmaf(sf, s_cx[tid], si * tg);
            s_cx[tid] = c;
            s_dh[tid].y = so * tanhf(c);
        }
        __syncthreads();

        // --- Phase 3: td[k] = tanh(hx . W2T[:,k]) ---
        {
            int k = tid & 127, q = tid >> 7;
            float p = 0.f;
#pragma unroll
            for (int hh = q * 32; hh < q * 32 + 32; hh++)
                p = fmaf(s_dh[hh].y, g_W2T[hh * HH + k], p);
            s_scr[tid] = p;
        }
        __syncthreads();
        if (tid < HH) {
            float td = tanhf(s_scr[tid] + s_scr[tid + 128] + s_scr[tid + 256] + s_scr[tid + 384]);
            s_td2[tid]  = make_float2(td, td);
            float vt = s_v[tid] * td;
            s_vtd2[tid] = make_float2(vt, vt);
        }
        __syncthreads();

        // --- Phase 4a: rational groups-of-4 + f32x2 (proven in round-6 bench) ---
        {
            int n4 = tid & 127, q = tid >> 7;
            const float4* tp = reinterpret_cast<const float4*>(teb + (size_t)(q * 32) * NN) + n4;
            float ax = 0.f, ay = 0.f, az = 0.f, aw = 0.f;
#pragma unroll
            for (int g = 0; g < 8; g++) {
                u64 numA = 0ull, denA = ONE2, numB = 0ull, denB = ONE2;
#pragma unroll
                for (int kk = 0; kk < 4; kk++) {
                    int k = q * 32 + g * 4 + kk;
                    float4 te = tp[(size_t)(g * 4 + kk) * (NN / 4)];
                    u64 teA = f2pack(te.x, te.y), teB = f2pack(te.z, te.w);
                    u64 td2 = *(const u64*)&s_td2[k];
                    u64 vt2 = *(const u64*)&s_vtd2[k];
                    u64 vk2 = *(const u64*)&s_v2[k];
                    u64 nkA = f2fma(vk2, teA, vt2);        // v*te + v*td
                    u64 dkA = f2fma(teA, td2, ONE2);       // 1 + te*td
                    numA = f2fma(numA, dkA, f2mul(nkA, denA));
                    denA = f2mul(denA, dkA);
                    u64 nkB = f2fma(vk2, teB, vt2);
                    u64 dkB = f2fma(teB, td2, ONE2);
                    numB = f2fma(numB, dkB, f2mul(nkB, denB));
                    denB = f2mul(denB, dkB);
                }
                float nx, ny, dx, dy;
                f2unpack(numA, nx, ny); f2unpack(denA, dx, dy);
                ax += __fdividef(nx, dx); ay += __fdividef(ny, dy);
                f2unpack(numB, nx, ny); f2unpack(denB, dx, dy);
                az += __fdividef(nx, dx); aw += __fdividef(ny, dy);
            }
            reinterpret_cast<float4*>(s_scr)[q * 128 + n4] = make_float4(ax, ay, az, aw);
        }
        __syncthreads();

        // --- Phase 4b: combine partials + table gumbel + fused argmax/scoremax reduce ---
        float sm;
        {
            float sc = s_scr[tid] + s_scr[NN + tid] + s_scr[2 * NN + tid] + s_scr[3 * NN + tid];
            float gum = __ldg(&g_gum[((size_t)(b * TT + t) << 9) + tid]);

            sm = s_mask[tid] ? NEG_INF : sc;
            s_score[tid] = sm;
            float mv = sm + gum;
            int   mi = tid;
            float sx = sm;
#pragma unroll
            for (int off = 16; off; off >>= 1) {
                float ov = __shfl_down_sync(0xffffffffu, mv, off);
                int   oi = __shfl_down_sync(0xffffffffu, mi, off);
                float os = __shfl_down_sync(0xffffffffu, sx, off);
                if (ov > mv || (ov == mv && oi < mi)) { mv = ov; mi = oi; }
                sx = fmaxf(sx, os);
            }
            if (lane == 0) { s_rw[wid] = mv; s_ri[wid] = mi; s_rm[wid] = sx; }
        }
        __syncthreads();
        if (wid == 0) {
            float mv = (lane < 16) ? s_rw[lane] : NEG_INF;
            int   mi = (lane < 16) ? s_ri[lane] : 0x7fffffff;
            float sx = (lane < 16) ? s_rm[lane] : NEG_INF;
#pragma unroll
            for (int off = 16; off; off >>= 1) {
                float ov = __shfl_down_sync(0xffffffffu, mv, off);
                int   oi = __shfl_down_sync(0xffffffffu, mi, off);
                float os = __shfl_down_sync(0xffffffffu, sx, off);
                if (ov > mv || (ov == mv && oi < mi)) { mv = ov; mi = oi; }
                sx = fmaxf(sx, os);
            }
            if (lane == 0) { s_sel = mi; s_smax = sx; }
        }
        __syncthreads();

        // --- softmax denominator ---
        {
            float e = expf(sm - s_smax);
#pragma unroll
            for (int off = 16; off; off >>= 1)
                e += __shfl_down_sync(0xffffffffu, e, off);
            if (lane == 0) s_rw[wid] = e;
        }
        __syncthreads();

        if (tid == 0) {
            float tot = 0.f;
#pragma unroll
            for (int i = 0; i < 16; i++) tot += s_rw[i];
            int sel = s_sel;
            float prob = expf(s_score[sel] - s_smax) / tot;
            out[b * TT + t]           = (float)sel;
            out[BB * TT + b * TT + t] = logf(prob + 1e-9f);
            s_mask[sel] = 1;
        }
        __syncthreads();

        if (tid < HH)
            s_dh[tid].x = enc[((size_t)b * NN + s_sel) * HH + tid];
        __syncthreads();
    }
}

// ------------------------- launcher -------------------------
extern "C" void kernel_launch(void* const* d_in, const int* in_sizes, int n_in,
                              void* d_out, int out_size) {
    const float* enc  = (const float*)d_in[0];
    const float* W_ih = (const float*)d_in[1];
    const float* W_hh = (const float*)d_in[2];
    const float* b_ih = (const float*)d_in[3];
    const float* b_hh = (const float*)d_in[4];
    const float* W1   = (const float*)d_in[5];
    const float* W2   = (const float*)d_in[6];
    const float* v    = (const float*)d_in[7];
    (void)in_sizes; (void)n_in; (void)out_size;

    const int smem = SH * G4 * sizeof(float2);   // 212992 bytes
    cudaFuncSetAttribute(k_decode, cudaFuncAttributeMaxDynamicSharedMemorySize, smem);

    k_prep<<<64, 256>>>(W_ih, W_hh, W1, W2);
    k_gum<<<BB * TT * NN / 512, 512>>>();
    k_enc<<<dim3(16, BB), 128>>>(enc);
    k_decode<<<BB, 512, smem>>>(enc, b_ih, b_hh, v, (float*)d_out);
}

// round 11
// speedup vs baseline: 2.4765x; 1.1221x over previous
#include <cuda_runtime.h>
#include <math.h>

#define BB 128
#define NN 512
#define HH 128
#define TT 32
#define G4 512
#define SH 52      // weight hh-rows cached in smem (52 rows, paired into 26 x 16B)
#define REGR 28    // weight hh-rows cached in registers (rows 52..79)
// rows 80..127 streamed from L2 each step

typedef unsigned long long u64;

// ------------------------- device scratch -------------------------
__device__ float  g_te[(size_t)BB * HH * NN];   // tanh(enc_trans): [b][k][n]
__device__ float2 g_Wc[HH * G4];                // [hh][j] = {Wih[j][hh], Whh[j][hh]}
__device__ float  g_W2T[HH * HH];               // [hh][k]
__device__ float  g_W1T[HH * HH];               // [hh][k]
__device__ unsigned g_sub[TT * 2];
__device__ float  g_gum[BB * TT * NN];          // precomputed gumbel noise (8 MB)

// ------------------------- f32x2 packed math (sm_100+) -------------------------
__device__ __forceinline__ u64 f2pack(float x, float y) {
    u64 r; asm("mov.b64 %0,{%1,%2};" : "=l"(r) : "f"(x), "f"(y)); return r;
}
__device__ __forceinline__ void f2unpack(u64 p, float& x, float& y) {
    asm("mov.b64 {%0,%1},%2;" : "=f"(x), "=f"(y) : "l"(p));
}
__device__ __forceinline__ u64 f2fma(u64 a, u64 b, u64 c) {
    u64 d; asm("fma.rn.f32x2 %0,%1,%2,%3;" : "=l"(d) : "l"(a), "l"(b), "l"(c)); return d;
}
__device__ __forceinline__ u64 f2mul(u64 a, u64 b) {
    u64 d; asm("mul.rn.f32x2 %0,%1,%2;" : "=l"(d) : "l"(a), "l"(b)); return d;
}

// ------------------------- Threefry-2x32 (JAX partitionable) -------------------------
__device__ __forceinline__ unsigned rotl32(unsigned x, int r) {
    return (x << r) | (x >> (32 - r));
}
__device__ __forceinline__ void tf2x32(unsigned k0, unsigned k1,
                                       unsigned x0, unsigned x1,
                                       unsigned& o0, unsigned& o1) {
    unsigned ks2 = k0 ^ k1 ^ 0x1BD11BDAu;
    x0 += k0; x1 += k1;
#define TF_RND(r) { x0 += x1; x1 = rotl32(x1, r); x1 ^= x0; }
    TF_RND(13) TF_RND(15) TF_RND(26) TF_RND(6)
    x0 += k1; x1 += ks2 + 1u;
    TF_RND(17) TF_RND(29) TF_RND(16) TF_RND(24)
    x0 += ks2; x1 += k0 + 2u;
    TF_RND(13) TF_RND(15) TF_RND(26) TF_RND(6)
    x0 += k0; x1 += k1 + 3u;
    TF_RND(17) TF_RND(29) TF_RND(16) TF_RND(24)
    x0 += k1; x1 += ks2 + 4u;
    TF_RND(13) TF_RND(15) TF_RND(26) TF_RND(6)
    x0 += ks2; x1 += k0 + 5u;
#undef TF_RND
    o0 = x0; o1 = x1;
}

// ------------------------- prep -------------------------
__global__ void k_prep(const float* __restrict__ W_ih, const float* __restrict__ W_hh,
                       const float* __restrict__ W1,   const float* __restrict__ W2) {
    int tid = blockIdx.x * blockDim.x + threadIdx.x;
    const int NT = 64 * 256;
    for (int i = tid; i < G4 * HH; i += NT) {
        int j = i / HH, hh = i % HH;
        g_Wc[hh * G4 + j] = make_float2(W_ih[i], W_hh[i]);
    }
    for (int i = tid; i < HH * HH; i += NT) {
        int k = i / HH, hh = i % HH;
        g_W2T[hh * HH + k] = W2[i];
        g_W1T[hh * HH + k] = W1[i];
    }
    if (tid == 0) {
        unsigned k0 = 0u, k1 = 42u;   // jax.random.key(42)
        for (int t = 0; t < TT; t++) {
            unsigned a0, a1, b0, b1;
            tf2x32(k0, k1, 0u, 0u, a0, a1);
            tf2x32(k0, k1, 0u, 1u, b0, b1);
            g_sub[2 * t] = b0; g_sub[2 * t + 1] = b1;
            k0 = a0; k1 = a1;
        }
    }
}

// ------------- enc_trans + gumbel table, one dual-role kernel (128 thr/block) -------------
// blocks [0, 2048):  enc role  (b = blk>>4, n0 = (blk&15)*32)
// blocks [2048, 6144): gum role (bt = blk-2048; 512 elems per block, 4 per thread)
__global__ __launch_bounds__(128) void k_encgum(const float* __restrict__ enc) {
    __shared__ float sAT[HH][36];   // [h][n] (enc role only)
    if (blockIdx.x >= 2048) {
        int bt = blockIdx.x - 2048;          // = b*TT + t
        int t = bt & 31, b = bt >> 5;
        unsigned sk0 = g_sub[2 * t], sk1 = g_sub[2 * t + 1];
        int n0 = threadIdx.x * 4;
        float4 r;
        float* rr = &r.x;
#pragma unroll
        for (int i = 0; i < 4; i++) {
            unsigned o0, o1;
            tf2x32(sk0, sk1, 0u, (unsigned)(b * NN + n0 + i), o0, o1);
            unsigned bits = o0 ^ o1;
            float u = fmaxf(1.17549435e-38f, __uint_as_float((bits >> 9) | 0x3f800000u) - 1.0f);
            rr[i] = -logf(-logf(u));
        }
        ((float4*)g_gum)[(size_t)bt * 128 + threadIdx.x] = r;
        return;
    }

    const int b  = blockIdx.x >> 4;
    const int n0 = (blockIdx.x & 15) * 32;
    {
        const float4* src = (const float4*)(enc + ((size_t)b * NN + n0) * HH);
        for (int i = threadIdx.x; i < 32 * 32; i += 128) {
            int n = i >> 5, h4 = (i & 31) << 2;
            float4 vv = src[i];
            sAT[h4 + 0][n] = vv.x;
            sAT[h4 + 1][n] = vv.y;
            sAT[h4 + 2][n] = vv.z;
            sAT[h4 + 3][n] = vv.w;
        }
    }
    __syncthreads();

    const int k = threadIdx.x;
    u64 acc[16];
    const u64 Z = f2pack(0.f, 0.f);
#pragma unroll
    for (int i = 0; i < 16; i++) acc[i] = Z;

#pragma unroll 4
    for (int h = 0; h < HH; h++) {
        float w = __ldg(&g_W1T[h * HH + k]);
        u64 wd = f2pack(w, w);
        const ulonglong2* row = (const ulonglong2*)&sAT[h][0];
#pragma unroll
        for (int i = 0; i < 8; i++) {
            ulonglong2 q = row[i];
            acc[2 * i]     = f2fma(q.x, wd, acc[2 * i]);
            acc[2 * i + 1] = f2fma(q.y, wd, acc[2 * i + 1]);
        }
    }
    float2* dst = (float2*)(g_te + ((size_t)b * HH + k) * NN + n0);
#pragma unroll
    for (int i = 0; i < 16; i++) {
        float a, bb;
        f2unpack(acc[i], a, bb);
        dst[i] = make_float2(tanhf(a), tanhf(bb));
    }
}

// ------------------------- persistent per-batch decode -------------------------
__global__ __launch_bounds__(512, 1) void k_decode(const float* __restrict__ enc,
                                                   const float* __restrict__ b_ih,
                                                   const float* __restrict__ b_hh,
                                                   const float* __restrict__ v,
                                                   float* __restrict__ out) {
    extern __shared__ ulonglong2 s_wc[];       // [26 * G4] paired weight rows (208 KB)
    __shared__ float2 s_dh[HH];                // {dec, hx}
    __shared__ float  s_cx[HH], s_v[HH];
    __shared__ float2 s_td2[HH];               // {td, td}
    __shared__ float2 s_vtd2[HH];              // {v*td, v*td}
    __shared__ float2 s_v2[HH];                // {v, v}
    __shared__ float  s_score[NN];
    __shared__ float  s_scr[4 * NN];           // scratch (8 KB)
    __shared__ unsigned char s_mask[NN];
    __shared__ float  s_rw[16];
    __shared__ int    s_ri[16];
    __shared__ float  s_rm[16];
    __shared__ int    s_sel;
    __shared__ float  s_smax;

    const int b = blockIdx.x;
    const int tid = threadIdx.x;
    const int lane = tid & 31, wid = tid >> 5;
    const float NEG_INF = __int_as_float(0xff800000);

    // one-time smem weight cache fill: pair rows (2p, 2p+1) into one 16B slot
    for (int i = tid; i < (SH / 2) * G4; i += 512) {
        int p = i >> 9, j = i & 511;
        float2 a = g_Wc[(2 * p) * G4 + j];
        float2 c = g_Wc[(2 * p + 1) * G4 + j];
        ulonglong2 w;
        w.x = *(u64*)&a; w.y = *(u64*)&c;
        s_wc[p * G4 + j] = w;
    }
    // register weight cache: rows SH..SH+REGR-1, this thread's j-column
    u64 rwc[REGR];
#pragma unroll
    for (int i = 0; i < REGR; i++) {
        float2 w = __ldg(&g_Wc[(SH + i) * G4 + tid]);
        rwc[i] = f2pack(w.x, w.y);
    }
    // register W2T cache: this thread's (k, hh-quarter) column, 32 floats
    const int p3k = tid & 127, p3q = tid >> 7;
    float rw2[32];
#pragma unroll
    for (int i = 0; i < 32; i++)
        rw2[i] = __ldg(&g_W2T[(p3q * 32 + i) * HH + p3k]);

    if (tid < HH) {
        s_cx[tid] = 0.f; s_dh[tid].y = 0.f;
        float vv = v[tid];
        s_v[tid] = vv;
        s_v2[tid] = make_float2(vv, vv);
    }
    s_mask[tid] = 0;

    // dec0 = mean over n of encoder_outputs[b]
    {
        int h = tid & 127, q = tid >> 7;
        const float* p = enc + ((size_t)b * NN + (size_t)q * 128) * HH + h;
        float sum = 0.f;
#pragma unroll 8
        for (int n = 0; n < 128; n++) sum += p[(size_t)n * HH];
        s_scr[tid] = sum;
        __syncthreads();
        if (tid < HH)
            s_dh[tid].x = (s_scr[tid] + s_scr[tid + 128] + s_scr[tid + 256] + s_scr[tid + 384]) * (1.0f / NN);
    }
    __syncthreads();

    const float* teb = g_te + (size_t)b * HH * NN;
    const float bias = b_ih[tid] + b_hh[tid];   // j = tid
    const u64 ONE2 = f2pack(1.f, 1.f);

    for (int t = 0; t < TT; t++) {
        // --- Phase 1: gates[j] via FFMA2; rows: smem(0..51) + regs(52..79) + stream(80..127) ---
        {
            u64 acc2 = f2pack(bias, 0.f);
            const u64* dh64 = (const u64*)s_dh;
            const ulonglong2* dh128 = (const ulonglong2*)s_dh;
#pragma unroll 2
            for (int p = 0; p < SH / 2; p++) {
                ulonglong2 w  = s_wc[p * G4 + tid];
                ulonglong2 dh = dh128[p];
                acc2 = f2fma(dh.x, w.x, acc2);
                acc2 = f2fma(dh.y, w.y, acc2);
            }
#pragma unroll
            for (int i = 0; i < REGR; i++)
                acc2 = f2fma(dh64[SH + i], rwc[i], acc2);
#pragma unroll 8
            for (int hh = SH + REGR; hh < HH; hh++) {
                float2 w = __ldg(&g_Wc[hh * G4 + tid]);
                acc2 = f2fma(dh64[hh], f2pack(w.x, w.y), acc2);
            }
            float ax, ay;
            f2unpack(acc2, ax, ay);
            s_scr[tid] = ax + ay;
        }
        __syncthreads();

        // --- Phase 2: LSTM cell (i,f,g,o) ---
        if (tid < HH) {
            float gi = s_scr[tid];
            float gf = s_scr[HH + tid];
            float gg = s_scr[2 * HH + tid];
            float go = s_scr[3 * HH + tid];
            float si = fmaf(0.5f, tanhf(0.5f * gi), 0.5f);
            float sf = fmaf(0.5f, tanhf(0.5f * gf), 0.5f);
            float tg = tanhf(gg);
            float so = fmaf(0.5f, tanhf(0.5f * go), 0.5f);
            float c  = fmaf(sf, s_cx[tid], si * tg);
            s_cx[tid] = c;
            s_dh[tid].y = so * tanhf(c);
        }
        __syncthreads();

        // --- Phase 3: td[k] = tanh(hx . W2T[:,k]) via register-cached W2T ---
        {
            float p = 0.f;
#pragma unroll
            for (int i = 0; i < 32; i++)
                p = fmaf(s_dh[p3q * 32 + i].y, rw2[i], p);
            s_scr[tid] = p;
        }
        __syncthreads();
        if (tid < HH) {
            float td = tanhf(s_scr[tid] + s_scr[tid + 128] + s_scr[tid + 256] + s_scr[tid + 384]);
            s_td2[tid]  = make_float2(td, td);
            float vt = s_v[tid] * td;
            s_vtd2[tid] = make_float2(vt, vt);
        }
        __syncthreads();

        // --- Phase 4a: rational groups-of-4 + f32x2 ---
        {
            int n4 = tid & 127, q = tid >> 7;
            const float4* tp = reinterpret_cast<const float4*>(teb + (size_t)(q * 32) * NN) + n4;
            float ax = 0.f, ay = 0.f, az = 0.f, aw = 0.f;
#pragma unroll
            for (int g = 0; g < 8; g++) {
                u64 numA = 0ull, denA = ONE2, numB = 0ull, denB = ONE2;
#pragma unroll
                for (int kk = 0; kk < 4; kk++) {
                    int k = q * 32 + g * 4 + kk;
                    float4 te = tp[(size_t)(g * 4 + kk) * (NN / 4)];
                    u64 teA = f2pack(te.x, te.y), teB = f2pack(te.z, te.w);
                    u64 td2 = *(const u64*)&s_td2[k];
                    u64 vt2 = *(const u64*)&s_vtd2[k];
                    u64 vk2 = *(const u64*)&s_v2[k];
                    u64 nkA = f2fma(vk2, teA, vt2);        // v*te + v*td
                    u64 dkA = f2fma(teA, td2, ONE2);       // 1 + te*td
                    numA = f2fma(numA, dkA, f2mul(nkA, denA));
                    denA = f2mul(denA, dkA);
                    u64 nkB = f2fma(vk2, teB, vt2);
                    u64 dkB = f2fma(teB, td2, ONE2);
                    numB = f2fma(numB, dkB, f2mul(nkB, denB));
                    denB = f2mul(denB, dkB);
                }
                float nx, ny, dx, dy;
                f2unpack(numA, nx, ny); f2unpack(denA, dx, dy);
                ax += __fdividef(nx, dx); ay += __fdividef(ny, dy);
                f2unpack(numB, nx, ny); f2unpack(denB, dx, dy);
                az += __fdividef(nx, dx); aw += __fdividef(ny, dy);
            }
            reinterpret_cast<float4*>(s_scr)[q * 128 + n4] = make_float4(ax, ay, az, aw);
        }
        __syncthreads();

        // --- Phase 4b: combine partials + table gumbel + fused argmax/scoremax reduce ---
        float sm;
        {
            float sc = s_scr[tid] + s_scr[NN + tid] + s_scr[2 * NN + tid] + s_scr[3 * NN + tid];
            float gum = __ldg(&g_gum[((size_t)(b * TT + t) << 9) + tid]);

            sm = s_mask[tid] ? NEG_INF : sc;
            s_score[tid] = sm;
            float mv = sm + gum;
            int   mi = tid;
            float sx = sm;
#pragma unroll
            for (int off = 16; off; off >>= 1) {
                float ov = __shfl_down_sync(0xffffffffu, mv, off);
                int   oi = __shfl_down_sync(0xffffffffu, mi, off);
                float os = __shfl_down_sync(0xffffffffu, sx, off);
                if (ov > mv || (ov == mv && oi < mi)) { mv = ov; mi = oi; }
                sx = fmaxf(sx, os);
            }
            if (lane == 0) { s_rw[wid] = mv; s_ri[wid] = mi; s_rm[wid] = sx; }
        }
        __syncthreads();
        if (wid == 0) {
            float mv = (lane < 16) ? s_rw[lane] : NEG_INF;
            int   mi = (lane < 16) ? s_ri[lane] : 0x7fffffff;
            float sx = (lane < 16) ? s_rm[lane] : NEG_INF;
#pragma unroll
            for (int off = 16; off; off >>= 1) {
                float ov = __shfl_down_sync(0xffffffffu, mv, off);
                int   oi = __shfl_down_sync(0xffffffffu, mi, off);
                float os = __shfl_down_sync(0xffffffffu, sx, off);
                if (ov > mv || (ov == mv && oi < mi)) { mv = ov; mi = oi; }
                sx = fmaxf(sx, os);
            }
            if (lane == 0) { s_sel = mi; s_smax = sx; }
        }
        __syncthreads();

        // --- softmax denominator ---
        {
            float e = expf(sm - s_smax);
#pragma unroll
            for (int off = 16; off; off >>= 1)
                e += __shfl_down_sync(0xffffffffu, e, off);
            if (lane == 0) s_rw[wid] = e;
        }
        __syncthreads();

        if (tid == 0) {
            float tot = 0.f;
#pragma unroll
            for (int i = 0; i < 16; i++) tot += s_rw[i];
            int sel = s_sel;
            float prob = expf(s_score[sel] - s_smax) / tot;
            out[b * TT + t]           = (float)sel;
            out[BB * TT + b * TT + t] = logf(prob + 1e-9f);
            s_mask[sel] = 1;
        }
        __syncthreads();

        if (tid < HH)
            s_dh[tid].x = enc[((size_t)b * NN + s_sel) * HH + tid];
        __syncthreads();
    }
}

// ------------------------- launcher -------------------------
extern "C" void kernel_launch(void* const* d_in, const int* in_sizes, int n_in,
                              void* d_out, int out_size) {
    const float* enc  = (const float*)d_in[0];
    const float* W_ih = (const float*)d_in[1];
    const float* W_hh = (const float*)d_in[2];
    const float* b_ih = (const float*)d_in[3];
    const float* b_hh = (const float*)d_in[4];
    const float* W1   = (const float*)d_in[5];
    const float* W2   = (const float*)d_in[6];
    const float* v    = (const float*)d_in[7];
    (void)in_sizes; (void)n_in; (void)out_size;

    const int smem = (SH / 2) * G4 * sizeof(ulonglong2);   // 212992 bytes
    cudaFuncSetAttribute(k_decode, cudaFuncAttributeMaxDynamicSharedMemorySize, smem);

    k_prep<<<64, 256>>>(W_ih, W_hh, W1, W2);
    k_encgum<<<2048 + BB * TT, 128>>>(enc);
    k_decode<<<BB, 512, smem>>>(enc, b_ih, b_hh, v, (float*)d_out);
}